// round 3
// baseline (speedup 1.0000x reference)
#include <cuda_runtime.h>
#include <math.h>

// Problem constants (fixed by setup_inputs)
#define NB    1024          // batch
#define CCH   128           // channels
#define HIM   64            // image H
#define WIM   64            // image W
#define NPIX  1024          // 32*32 grid pixels
#define KF    0.3f
#define OFF   0.35f         // (1-KF)/2
#define G     8             // batch items per sampling group
#define NGROUPS 136         // max groups: 128 + 8 (per-bucket padding)

typedef unsigned long long u64;

// ---------------- device scratch (no allocations allowed) ----------------
__device__ float g_h1[NB * 512];
__device__ float g_h2[NB * 256];
__device__ float g_h3[NB * 256];
__device__ float g_theta[NB * 36];
__device__ float g_vmm[NB * 4];          // vminx, vminy, vmaxx, vmaxy
__device__ uint2 g_coords[NB * NPIX];    // packed warped coords
__device__ int   g_list[NGROUPS * G];    // n indices per group (-1 = pad)
__device__ int   g_gimg[NGROUPS];        // image id per group

// ---------------- per-n min/max over polargrid ----------------
__global__ __launch_bounds__(256) void minmax_kernel(const float* __restrict__ pg)
{
    const int n = blockIdx.x;
    const float2* p = (const float2*)pg + (size_t)n * NPIX;
    float mnx = 1e30f, mny = 1e30f, mxx = -1e30f, mxy = -1e30f;
    for (int i = threadIdx.x; i < NPIX; i += 256) {
        float2 v = p[i];
        mnx = fminf(mnx, v.x); mxx = fmaxf(mxx, v.x);
        mny = fminf(mny, v.y); mxy = fmaxf(mxy, v.y);
    }
#pragma unroll
    for (int o = 16; o > 0; o >>= 1) {
        mnx = fminf(mnx, __shfl_xor_sync(0xffffffffu, mnx, o));
        mny = fminf(mny, __shfl_xor_sync(0xffffffffu, mny, o));
        mxx = fmaxf(mxx, __shfl_xor_sync(0xffffffffu, mxx, o));
        mxy = fmaxf(mxy, __shfl_xor_sync(0xffffffffu, mxy, o));
    }
    __shared__ float red[8][4];
    int w = threadIdx.x >> 5, l = threadIdx.x & 31;
    if (l == 0) { red[w][0] = mnx; red[w][1] = mny; red[w][2] = mxx; red[w][3] = mxy; }
    __syncthreads();
    if (threadIdx.x == 0) {
        for (int i = 1; i < 8; i++) {
            mnx = fminf(mnx, red[i][0]); mny = fminf(mny, red[i][1]);
            mxx = fmaxf(mxx, red[i][2]); mxy = fmaxf(mxy, red[i][3]);
        }
        g_vmm[n * 4 + 0] = mnx; g_vmm[n * 4 + 1] = mny;
        g_vmm[n * 4 + 2] = mxx; g_vmm[n * 4 + 3] = mxy;
    }
}

// ---------------- group n's by image id (counting sort, 1 block) ----------
__global__ __launch_bounds__(256) void prep_groups(const int* __restrict__ ids)
{
    __shared__ int cnt[8], base[8], off[8];
    const int t = threadIdx.x;
    if (t < 8) { cnt[t] = 0; off[t] = 0; }
    __syncthreads();
    for (int i = t; i < NB; i += 256) atomicAdd(&cnt[ids[i]], 1);
    for (int i = t; i < NGROUPS * G; i += 256) g_list[i] = -1;
    for (int i = t; i < NGROUPS; i += 256) g_gimg[i] = 0;
    __syncthreads();
    if (t == 0) {
        int p = 0;
        for (int k = 0; k < 8; k++) {
            base[k] = p;
            const int ng = (cnt[k] + G - 1) / G;
            for (int j = 0; j < ng; j++) g_gimg[p / G + j] = k;
            p += ng * G;
        }
    }
    __syncthreads();
    for (int i = t; i < NB; i += 256) {
        const int k = ids[i];
        const int r = atomicAdd(&off[k], 1);
        g_list[base[k] + r] = i;
    }
}

// ---------------- fp32 GEMM, f32x2 inner loop, B pre-duplicated in smem ----
// C = act(A @ W + bias). A: MxK row-major, W: KxN row-major.
// BM=64, BN=32, BK=32, 256 thr. Thread: 4 rows (2 u64 row-pairs) x 2 cols.
#define BM 64
#define BN 32
#define BK 32

#define FFMA2(ACCV, AV, BV) \
    asm("fma.rn.f32x2 %0, %1, %2, %0;" : "+l"(ACCV) : "l"(AV), "l"(BV))

template<int ACT>  // 0 = relu, 1 = tanh
__global__ __launch_bounds__(256) void gemm_act(
    const float* __restrict__ A, const float* __restrict__ W,
    const float* __restrict__ bias, float* __restrict__ C,
    int M, int K, int N)
{
    __shared__ float As[BK][BM];        // k-major: row-pairs contiguous
    __shared__ float Bd[BK][BN * 2];    // duplicated pairs (b,b)

    const int tid = threadIdx.x;
    const int bm = blockIdx.y * BM;
    const int bn = blockIdx.x * BN;
    const int tx = tid & 15;        // cols bn + tx*2 .. +1
    const int ty = tid >> 4;        // rows bm + ty*4 .. +3

    // A loader: 2 float4 per thread; flat f in [0,512): row=f>>3, kc=(f&7)*4
    const int ar0 = (tid * 2) >> 3;
    const int ak0 = ((tid * 2) & 7) * 4;
    const int ar1 = (tid * 2 + 1) >> 3;
    const int ak1 = ((tid * 2 + 1) & 7) * 4;
    // B loader: 1 float4 per thread: krow=tid>>3, col4=(tid&7)*4
    const int kr = tid >> 3;
    const int bc = (tid & 7) * 4;

    u64 acc[2][2] = {};   // [row-pair][col]

    for (int k0 = 0; k0 < K; k0 += BK) {
        // load A tile
        {
            const float4 v0 = *(const float4*)(A + (size_t)(bm + ar0) * K + k0 + ak0);
            As[ak0 + 0][ar0] = v0.x; As[ak0 + 1][ar0] = v0.y;
            As[ak0 + 2][ar0] = v0.z; As[ak0 + 3][ar0] = v0.w;
            const float4 v1 = *(const float4*)(A + (size_t)(bm + ar1) * K + k0 + ak1);
            As[ak1 + 0][ar1] = v1.x; As[ak1 + 1][ar1] = v1.y;
            As[ak1 + 2][ar1] = v1.z; As[ak1 + 3][ar1] = v1.w;
        }
        // load B tile, duplicated
        {
            const int col = bn + bc;
            const float* wptr = W + (size_t)(k0 + kr) * N + col;
            float4 wv;
            if (col + 3 < N) {
                wv = *(const float4*)wptr;
            } else {
                wv.x = (col + 0 < N) ? wptr[0] : 0.f;
                wv.y = (col + 1 < N) ? wptr[1] : 0.f;
                wv.z = (col + 2 < N) ? wptr[2] : 0.f;
                wv.w = (col + 3 < N) ? wptr[3] : 0.f;
            }
            float4* bp = (float4*)&Bd[kr][bc * 2];
            bp[0] = make_float4(wv.x, wv.x, wv.y, wv.y);
            bp[1] = make_float4(wv.z, wv.z, wv.w, wv.w);
        }
        __syncthreads();

#pragma unroll
        for (int k = 0; k < BK; k++) {
            const u64* ap = (const u64*)&As[k][ty * 4];
            const u64 a01 = ap[0];
            const u64 a23 = ap[1];
            const u64* bp = (const u64*)&Bd[k][tx * 4];
            const u64 b0 = bp[0];
            const u64 b1 = bp[1];
            FFMA2(acc[0][0], a01, b0);
            FFMA2(acc[1][0], a23, b0);
            FFMA2(acc[0][1], a01, b1);
            FFMA2(acc[1][1], a23, b1);
        }
        __syncthreads();
    }

#pragma unroll
    for (int p = 0; p < 2; p++) {
#pragma unroll
        for (int j = 0; j < 2; j++) {
            float lo, hi;
            asm("mov.b64 {%0, %1}, %2;" : "=f"(lo), "=f"(hi) : "l"(acc[p][j]));
            const int col = bn + tx * 2 + j;
            if (col < N) {
                const float bv = bias[col];
                const int r0 = bm + ty * 4 + p * 2;
                float v0 = lo + bv, v1 = hi + bv;
                v0 = (ACT == 0) ? fmaxf(v0, 0.f) : tanhf(v0);
                v1 = (ACT == 0) ? fmaxf(v1, 0.f) : tanhf(v1);
                C[(size_t)r0 * N + col] = v0;
                C[(size_t)(r0 + 1) * N + col] = v1;
            }
        }
    }
}

// ---------------- TPS warp -> packed sample coords -------------------------
__global__ __launch_bounds__(256) void coords_kernel(const float* __restrict__ polargrid)
{
    __shared__ float s_ctrl[16][2];
    __shared__ float s_w[16][2];
    __shared__ float s_a[3][2];

    const int n = blockIdx.x;
    const int tid = threadIdx.x;

    const float vminx = g_vmm[n * 4 + 0];
    const float vminy = g_vmm[n * 4 + 1];
    const float ptpx  = g_vmm[n * 4 + 2] - vminx;
    const float ptpy  = g_vmm[n * 4 + 3] - vminy;
    const float sKx = KF / ptpx;
    const float sKy = KF / ptpy;

    if (tid < 2) {
        const int c = tid;
        const float* th = g_theta + (size_t)n * 36;
        float s = 0.f;
        for (int j = 0; j < 15; j++) {
            const float v = th[j * 2 + c];
            s += v;
            s_w[j + 1][c] = v;
        }
        s_w[0][c] = -s;
        s_a[0][c] = th[30 + c];
        s_a[1][c] = th[32 + c];
        s_a[2][c] = th[34 + c];
    }
    if (tid < 16) {
        const int ih = (tid >> 2) * 8, iw = (tid & 3) * 8;
        const float* p = polargrid + ((size_t)n * NPIX + ih * 32 + iw) * 2;
        s_ctrl[tid][0] = (p[0] - vminx) * sKx + OFF;
        s_ctrl[tid][1] = (p[1] - vminy) * sKy + OFF;
    }
    __syncthreads();

    const float2* pgp = (const float2*)polargrid + (size_t)n * NPIX;
#pragma unroll
    for (int q = 0; q < 4; q++) {
        const int p = tid + q * 256;
        const float2 g = pgp[p];
        const float pgx = (g.x - vminx) * sKx + OFF;
        const float pgy = (g.y - vminy) * sKy + OFF;
        float zx = s_a[0][0] + pgx * s_a[1][0] + pgy * s_a[2][0];
        float zy = s_a[0][1] + pgx * s_a[1][1] + pgy * s_a[2][1];
#pragma unroll
        for (int j = 0; j < 16; j++) {
            const float dx = pgx - s_ctrl[j][0];
            const float dy = pgy - s_ctrl[j][1];
            const float d2 = dx * dx + dy * dy;
            const float u = d2 * logf(sqrtf(d2) + 1e-6f);
            zx += u * s_w[j][0];
            zy += u * s_w[j][1];
        }
        float twx = pgx + zx;
        float twy = pgy + zy;
        twx = (twx - OFF) * (ptpx / KF) + vminx;
        twy = (twy - OFF) * (ptpy / KF) + vminy;
        const float ix = fminf(fmaxf(32.f * twx + 31.5f, 0.f), 63.f);
        const float iy = fminf(fmaxf(32.f * twy + 31.5f, 0.f), 63.f);
        const float x0f = floorf(ix), y0f = floorf(iy);
        const int x0 = (int)x0f, y0 = (int)y0f;
        const float wx = ix - x0f, wy = iy - y0f;
        const unsigned dxf = (x0 < WIM - 1) ? 1u : 0u;
        const unsigned dyf = (y0 < HIM - 1) ? 1u : 0u;
        const unsigned w0 = (unsigned)(y0 * WIM + x0) | (dxf << 12) | (dyf << 13);
        const unsigned wxq = (unsigned)(wx * 65535.f + 0.5f);
        const unsigned wyq = (unsigned)(wy * 65535.f + 0.5f);
        g_coords[(size_t)n * NPIX + p] = make_uint2(w0, wxq | (wyq << 16));
    }
}

// ---------------- grouped bilinear sampling, channel-paired tiles ----------
// Block = (group of G n's sharing one image) x (half of the 64 channel-pairs).
// Tile holds float2(ch_c, ch_{c+64}); each tap = 1 LDS.64 for 2 channels.
__global__ __launch_bounds__(256, 2) void sample_kernel(
    const float* __restrict__ imgs, float* __restrict__ out)
{
    __shared__ float2 tile[HIM * WIM];    // 32 KB
    __shared__ int s_n[G];
    __shared__ int s_img;

    const int grp  = blockIdx.x >> 1;
    const int half = blockIdx.x & 1;
    const int tid  = threadIdx.x;

    if (tid < G) s_n[tid] = g_list[grp * G + tid];
    if (tid == 0) s_img = g_gimg[grp];
    __syncthreads();

    if (s_n[0] < 0) return;   // unused group

    int n_r[G];
#pragma unroll
    for (int i = 0; i < G; i++) n_r[i] = s_n[i];

    // packed coords for this block's 8192 pixels -> registers
    unsigned cw0[32], cw1[32];
#pragma unroll
    for (int q = 0; q < 32; q++) {
        const int n = n_r[q >> 2];
        if (n >= 0) {
            const uint2 c = g_coords[(size_t)n * NPIX + ((q & 3) << 8) + tid];
            cw0[q] = c.x; cw1[q] = c.y;
        } else { cw0[q] = 0; cw1[q] = 0; }
    }

    const int cbeg = half * 32;   // channel pairs (cbeg+ci, cbeg+ci+64)
    const float* imgA = imgs + (size_t)s_img * (CCH * HIM * WIM) + (size_t)cbeg * (HIM * WIM);
    const float* imgB = imgA + 64 * (HIM * WIM);

    for (int ci = 0; ci < 32; ci++) {
        // stage interleaved channel-pair tile
        const float4* a4 = (const float4*)(imgA + (size_t)ci * (HIM * WIM));
        const float4* b4 = (const float4*)(imgB + (size_t)ci * (HIM * WIM));
        float4* t4 = (float4*)tile;
#pragma unroll
        for (int j = 0; j < 4; j++) {
            const int f = tid + j * 256;
            const float4 a = a4[f];
            const float4 b = b4[f];
            t4[f * 2 + 0] = make_float4(a.x, b.x, a.y, b.y);
            t4[f * 2 + 1] = make_float4(a.z, b.z, a.w, b.w);
        }
        __syncthreads();

        const u64* tl = (const u64*)tile;
        const int cA = cbeg + ci;
#pragma unroll
        for (int q = 0; q < 32; q++) {
            const int n = n_r[q >> 2];
            if (n < 0) continue;
            const unsigned a = cw0[q], b = cw1[q];
            const int o  = a & 0xFFF;
            const int dx = (a >> 12) & 1;
            const int dy = ((a >> 13) & 1) << 6;
            const float wx  = (float)(b & 0xFFFF) * (1.f / 65535.f);
            const float wy  = (float)(b >> 16)    * (1.f / 65535.f);
            const float iwx = 1.f - wx;
            const float iwy = 1.f - wy;
            u64 wx2, iwx2, wy2, iwy2;
            asm("mov.b64 %0,{%1,%1};" : "=l"(wx2)  : "f"(wx));
            asm("mov.b64 %0,{%1,%1};" : "=l"(iwx2) : "f"(iwx));
            asm("mov.b64 %0,{%1,%1};" : "=l"(wy2)  : "f"(wy));
            asm("mov.b64 %0,{%1,%1};" : "=l"(iwy2) : "f"(iwy));

            const u64 v00 = tl[o];
            const u64 v01 = tl[o + dx];
            const u64 v10 = tl[o + dy];
            const u64 v11 = tl[o + dy + dx];

            u64 top, bot, res;
            asm("mul.rn.f32x2 %0, %1, %2;" : "=l"(top) : "l"(v01), "l"(wx2));
            FFMA2(top, v00, iwx2);
            asm("mul.rn.f32x2 %0, %1, %2;" : "=l"(bot) : "l"(v11), "l"(wx2));
            FFMA2(bot, v10, iwx2);
            asm("mul.rn.f32x2 %0, %1, %2;" : "=l"(res) : "l"(bot), "l"(wy2));
            FFMA2(res, top, iwy2);

            float rA, rB;
            asm("mov.b64 {%0, %1}, %2;" : "=f"(rA), "=f"(rB) : "l"(res));
            float* op = out + ((size_t)(unsigned)n << 17) + ((size_t)cA << 10)
                            + ((q & 3) << 8) + tid;
            op[0] = rA;
            op[64 << 10] = rB;
        }
        __syncthreads();
    }
}

// ---------------- launch ----------------
extern "C" void kernel_launch(void* const* d_in, const int* in_sizes, int n_in,
                              void* d_out, int out_size)
{
    const float* polargrid = (const float*)d_in[0];
    const float* xt        = (const float*)d_in[1];
    const float* imgs      = (const float*)d_in[2];
    const int*   imgIDs    = (const int*)  d_in[3];
    const float* W1 = (const float*)d_in[4];
    const float* b1 = (const float*)d_in[5];
    const float* W2 = (const float*)d_in[6];
    const float* b2 = (const float*)d_in[7];
    const float* W3 = (const float*)d_in[8];
    const float* b3 = (const float*)d_in[9];
    const float* W4 = (const float*)d_in[10];
    const float* b4 = (const float*)d_in[11];
    float* out = (float*)d_out;

    float *h1, *h2, *h3, *theta;
    cudaGetSymbolAddress((void**)&h1, g_h1);
    cudaGetSymbolAddress((void**)&h2, g_h2);
    cudaGetSymbolAddress((void**)&h3, g_h3);
    cudaGetSymbolAddress((void**)&theta, g_theta);

    minmax_kernel<<<NB, 256>>>(polargrid);
    prep_groups<<<1, 256>>>(imgIDs);

    gemm_act<0><<<dim3(512 / BN, NB / BM), 256>>>(xt, W1, b1, h1, NB, 3200, 512);
    gemm_act<0><<<dim3(256 / BN, NB / BM), 256>>>(h1, W2, b2, h2, NB, 512, 256);
    gemm_act<0><<<dim3(256 / BN, NB / BM), 256>>>(h2, W3, b3, h3, NB, 256, 256);
    gemm_act<1><<<dim3((36 + BN - 1) / BN, NB / BM), 256>>>(h3, W4, b4, theta, NB, 256, 36);

    coords_kernel<<<NB, 256>>>(polargrid);
    sample_kernel<<<NGROUPS * 2, 256>>>(imgs, out);
}

// round 4
// speedup vs baseline: 1.7703x; 1.7703x over previous
#include <cuda_runtime.h>
#include <cuda_fp16.h>
#include <math.h>

// Problem constants (fixed by setup_inputs)
#define NB    1024          // batch
#define CCH   128           // channels
#define HIM   64            // image H
#define WIM   64            // image W
#define IMPIX 4096          // 64*64
#define NPIX  1024          // 32*32 grid pixels
#define KF    0.3f
#define OFF   0.35f         // (1-KF)/2
#define G     8             // batch items per sampling group
#define NGROUPS 136         // 128 + 8 padding
#define KS    4             // split-K factor

typedef unsigned long long u64;
typedef unsigned int u32;

// ---------------- device scratch (no allocations allowed) ----------------
__device__ float g_h1[NB * 512];
__device__ float g_h2[NB * 256];
__device__ float g_h3[NB * 256];
__device__ float g_theta[NB * 36];
__device__ float g_part[KS * NB * 512];      // split-K partials (8MB, reused)
__device__ uint2 g_coords[NB * NPIX];        // packed warped coords
__device__ int   g_list[NGROUPS * G];        // n indices per group (-1 = pad)
__device__ int   g_gimg[NGROUPS];            // image id per group
__device__ u64   g_imgH[8 * 32 * IMPIX];     // fp16 4-ch interleaved images (8MB)

// ---------------- group n's by image id (counting sort, 1 block) ----------
__global__ __launch_bounds__(256) void prep_groups(const int* __restrict__ ids)
{
    __shared__ int cnt[8], base[8], off[8];
    const int t = threadIdx.x;
    if (t < 8) { cnt[t] = 0; off[t] = 0; }
    __syncthreads();
    for (int i = t; i < NB; i += 256) atomicAdd(&cnt[ids[i]], 1);
    for (int i = t; i < NGROUPS * G; i += 256) g_list[i] = -1;
    for (int i = t; i < NGROUPS; i += 256) g_gimg[i] = 0;
    __syncthreads();
    if (t == 0) {
        int p = 0;
        for (int k = 0; k < 8; k++) {
            base[k] = p;
            const int ng = (cnt[k] + G - 1) / G;
            for (int j = 0; j < ng; j++) g_gimg[p / G + j] = k;
            p += ng * G;
        }
    }
    __syncthreads();
    for (int i = t; i < NB; i += 256) {
        const int k = ids[i];
        const int r = atomicAdd(&off[k], 1);
        g_list[base[k] + r] = i;
    }
}

// ---------------- convert images to fp16 4-channel interleave -------------
// g_imgH[(k*32+c2)*4096 + pix] = u64{ half2(ch c, ch c+64), half2(ch c+1, ch c+65) }, c=2*c2
__global__ __launch_bounds__(256) void convert_kernel(const float* __restrict__ imgs)
{
    const int k  = blockIdx.x >> 5;
    const int c2 = blockIdx.x & 31;
    const int c  = c2 * 2;
    const float* p0 = imgs + ((size_t)k * CCH + c) * IMPIX;
    const float* p1 = p0 + IMPIX;
    const float* p2 = p0 + (size_t)64 * IMPIX;
    const float* p3 = p2 + IMPIX;
    u64* dst = g_imgH + ((size_t)(k * 32 + c2) << 12);

#pragma unroll
    for (int j = 0; j < 4; j++) {
        const int base = (j * 256 + threadIdx.x) * 4;
        const float4 v0 = *(const float4*)(p0 + base);
        const float4 v1 = *(const float4*)(p1 + base);
        const float4 v2 = *(const float4*)(p2 + base);
        const float4 v3 = *(const float4*)(p3 + base);
        const float a0[4] = { v0.x, v0.y, v0.z, v0.w };
        const float a1[4] = { v1.x, v1.y, v1.z, v1.w };
        const float a2[4] = { v2.x, v2.y, v2.z, v2.w };
        const float a3[4] = { v3.x, v3.y, v3.z, v3.w };
#pragma unroll
        for (int q = 0; q < 4; q++) {
            __half2 lo = __floats2half2_rn(a0[q], a2[q]);   // (c, c+64)
            __half2 hi = __floats2half2_rn(a1[q], a3[q]);   // (c+1, c+65)
            u32 ulo = *(u32*)&lo;
            u32 uhi = *(u32*)&hi;
            dst[base + q] = (u64)ulo | ((u64)uhi << 32);
        }
    }
}

// ---------------- split-K fp32 GEMM partial, f32x2 inner loop --------------
// partial[z] = A[:, z*Kc:(z+1)*Kc] @ W[z*Kc:(z+1)*Kc, :]
// BM=128, BN=64, BK=16, 256 thr; thread tile 8 rows x 4 cols.
#define GBM 128
#define GBN 64
#define GBK 16

#define FFMA2(ACCV, AV, BV) \
    asm("fma.rn.f32x2 %0, %1, %2, %0;" : "+l"(ACCV) : "l"(AV), "l"(BV))

__global__ __launch_bounds__(256) void gemm_partial(
    const float* __restrict__ A, const float* __restrict__ W,
    float* __restrict__ part, int M, int N, int K, int Kc)
{
    __shared__ float As[GBK][2 * GBM];   // A duplicated (a,a) pairs, 16KB
    __shared__ float Bs[GBK][GBN];       // 4KB

    const int tid = threadIdx.x;
    const int bm  = blockIdx.y * GBM;
    const int bn  = blockIdx.x * GBN;
    const int z   = blockIdx.z;
    const int ty  = tid >> 4;      // row group: rows ty*8..+7
    const int tx  = tid & 15;      // col group: cols tx*4..+3

    // A loader: 2 float4 per thread over 512 slots (128 rows x 4 quads)
    const int s0 = tid * 2,     ar0 = s0 >> 2, aq0 = (s0 & 3) * 4;
    const int s1 = tid * 2 + 1, ar1 = s1 >> 2, aq1 = (s1 & 3) * 4;
    // B loader: 1 float4 per thread
    const int kr = tid >> 4;
    const int bc = (tid & 15) * 4;

    u64 acc[8][2] = {};

    const int kbeg = z * Kc;
    const int kend = kbeg + Kc;
    for (int k0 = kbeg; k0 < kend; k0 += GBK) {
        {
            const float4 v0 = *(const float4*)(A + (size_t)(bm + ar0) * K + k0 + aq0);
            const float a0[4] = { v0.x, v0.y, v0.z, v0.w };
#pragma unroll
            for (int j = 0; j < 4; j++) {
                As[aq0 + j][2 * ar0]     = a0[j];
                As[aq0 + j][2 * ar0 + 1] = a0[j];
            }
            const float4 v1 = *(const float4*)(A + (size_t)(bm + ar1) * K + k0 + aq1);
            const float a1[4] = { v1.x, v1.y, v1.z, v1.w };
#pragma unroll
            for (int j = 0; j < 4; j++) {
                As[aq1 + j][2 * ar1]     = a1[j];
                As[aq1 + j][2 * ar1 + 1] = a1[j];
            }
        }
        {
            float4 wv = make_float4(0.f, 0.f, 0.f, 0.f);
            if (bn + bc < N)   // N is always a multiple of 4 here
                wv = *(const float4*)(W + (size_t)(k0 + kr) * N + bn + bc);
            *(float4*)&Bs[kr][bc] = wv;
        }
        __syncthreads();

#pragma unroll
        for (int k = 0; k < GBK; k++) {
            const u64* ap = (const u64*)&As[k][ty * 16];
            const u64* bp = (const u64*)&Bs[k][tx * 4];
            const u64 b01 = bp[0];
            const u64 b23 = bp[1];
            u64 ad[8];
#pragma unroll
            for (int r = 0; r < 8; r++) ad[r] = ap[r];
#pragma unroll
            for (int r = 0; r < 8; r++) {
                FFMA2(acc[r][0], ad[r], b01);
                FFMA2(acc[r][1], ad[r], b23);
            }
        }
        __syncthreads();
    }

    const int col = bn + tx * 4;
    if (col < N) {
#pragma unroll
        for (int r = 0; r < 8; r++) {
            const int row = bm + ty * 8 + r;
            float4 o;
            asm("mov.b64 {%0, %1}, %2;" : "=f"(o.x), "=f"(o.y) : "l"(acc[r][0]));
            asm("mov.b64 {%0, %1}, %2;" : "=f"(o.z), "=f"(o.w) : "l"(acc[r][1]));
            *(float4*)(part + ((size_t)z * M + row) * N + col) = o;
        }
    }
}

// epilogue: C = act(sum_z part[z] + bias)
template<int ACT>  // 0 = relu, 1 = tanh
__global__ __launch_bounds__(256) void gemm_epi(
    const float* __restrict__ part, const float* __restrict__ bias,
    float* __restrict__ C, int MN, int N)
{
    const int i = blockIdx.x * 256 + threadIdx.x;
    if (i >= MN) return;
    float s = part[i];
#pragma unroll
    for (int z = 1; z < KS; z++) s += part[(size_t)z * MN + i];
    s += bias[i % N];
    C[i] = (ACT == 0) ? fmaxf(s, 0.f) : tanhf(s);
}

// ---------------- minmax + TPS warp -> packed sample coords ----------------
__global__ __launch_bounds__(256) void coords_kernel(const float* __restrict__ polargrid)
{
    __shared__ float red[8][4];
    __shared__ float s_vm[4];
    __shared__ float s_ctrl[16][2];
    __shared__ float s_w[16][2];
    __shared__ float s_a[3][2];

    const int n = blockIdx.x;
    const int tid = threadIdx.x;

    // phase 0: minmax (keep the 4 float2 in registers for phase 1)
    const float2* pgp = (const float2*)polargrid + (size_t)n * NPIX;
    float2 g[4];
    float mnx = 1e30f, mny = 1e30f, mxx = -1e30f, mxy = -1e30f;
#pragma unroll
    for (int q = 0; q < 4; q++) {
        g[q] = pgp[tid + q * 256];
        mnx = fminf(mnx, g[q].x); mxx = fmaxf(mxx, g[q].x);
        mny = fminf(mny, g[q].y); mxy = fmaxf(mxy, g[q].y);
    }
#pragma unroll
    for (int o = 16; o > 0; o >>= 1) {
        mnx = fminf(mnx, __shfl_xor_sync(0xffffffffu, mnx, o));
        mny = fminf(mny, __shfl_xor_sync(0xffffffffu, mny, o));
        mxx = fmaxf(mxx, __shfl_xor_sync(0xffffffffu, mxx, o));
        mxy = fmaxf(mxy, __shfl_xor_sync(0xffffffffu, mxy, o));
    }
    const int w = tid >> 5, l = tid & 31;
    if (l == 0) { red[w][0] = mnx; red[w][1] = mny; red[w][2] = mxx; red[w][3] = mxy; }
    __syncthreads();
    if (tid == 0) {
        for (int i = 1; i < 8; i++) {
            mnx = fminf(mnx, red[i][0]); mny = fminf(mny, red[i][1]);
            mxx = fmaxf(mxx, red[i][2]); mxy = fmaxf(mxy, red[i][3]);
        }
        s_vm[0] = mnx; s_vm[1] = mny; s_vm[2] = mxx; s_vm[3] = mxy;
    }
    __syncthreads();

    const float vminx = s_vm[0];
    const float vminy = s_vm[1];
    const float ptpx  = s_vm[2] - vminx;
    const float ptpy  = s_vm[3] - vminy;
    const float sKx = KF / ptpx;
    const float sKy = KF / ptpy;

    if (tid < 2) {
        const int c = tid;
        const float* th = g_theta + (size_t)n * 36;
        float s = 0.f;
        for (int j = 0; j < 15; j++) {
            const float v = th[j * 2 + c];
            s += v;
            s_w[j + 1][c] = v;
        }
        s_w[0][c] = -s;
        s_a[0][c] = th[30 + c];
        s_a[1][c] = th[32 + c];
        s_a[2][c] = th[34 + c];
    }
    if (tid < 16) {
        const int ih = (tid >> 2) * 8, iw = (tid & 3) * 8;
        const float* p = polargrid + ((size_t)n * NPIX + ih * 32 + iw) * 2;
        s_ctrl[tid][0] = (p[0] - vminx) * sKx + OFF;
        s_ctrl[tid][1] = (p[1] - vminy) * sKy + OFF;
    }
    __syncthreads();

#pragma unroll
    for (int q = 0; q < 4; q++) {
        const int p = tid + q * 256;
        const float pgx = (g[q].x - vminx) * sKx + OFF;
        const float pgy = (g[q].y - vminy) * sKy + OFF;
        float zx = s_a[0][0] + pgx * s_a[1][0] + pgy * s_a[2][0];
        float zy = s_a[0][1] + pgx * s_a[1][1] + pgy * s_a[2][1];
#pragma unroll
        for (int j = 0; j < 16; j++) {
            const float dx = pgx - s_ctrl[j][0];
            const float dy = pgy - s_ctrl[j][1];
            const float d2 = dx * dx + dy * dy;
            const float u = d2 * logf(sqrtf(d2) + 1e-6f);
            zx += u * s_w[j][0];
            zy += u * s_w[j][1];
        }
        float twx = pgx + zx;
        float twy = pgy + zy;
        twx = (twx - OFF) * (ptpx / KF) + vminx;
        twy = (twy - OFF) * (ptpy / KF) + vminy;
        const float ix = fminf(fmaxf(32.f * twx + 31.5f, 0.f), 63.f);
        const float iy = fminf(fmaxf(32.f * twy + 31.5f, 0.f), 63.f);
        const float x0f = floorf(ix), y0f = floorf(iy);
        const int x0 = (int)x0f, y0 = (int)y0f;
        const float wx = ix - x0f, wy = iy - y0f;
        const unsigned dxf = (x0 < WIM - 1) ? 1u : 0u;
        const unsigned dyf = (y0 < HIM - 1) ? 1u : 0u;
        const unsigned w0 = (unsigned)(y0 * WIM + x0) | (dxf << 12) | (dyf << 13);
        const unsigned wxq = (unsigned)(wx * 65535.f + 0.5f);
        const unsigned wyq = (unsigned)(wy * 65535.f + 0.5f);
        g_coords[(size_t)n * NPIX + p] = make_uint2(w0, wxq | (wyq << 16));
    }
}

// ---------------- grouped bilinear sampling, fp16 4-channel tiles ----------
#define CP16(dst, src) \
    asm volatile("cp.async.ca.shared.global [%0], [%1], 16;" :: "r"(dst), "l"(src))

__global__ __launch_bounds__(256, 2) void sample_kernel(float* __restrict__ out)
{
    __shared__ u64 tile[2][IMPIX];       // 2 x 32KB double buffer
    __shared__ int s_n[G];
    __shared__ int s_img;

    const int grp  = blockIdx.x >> 1;
    const int half = blockIdx.x & 1;
    const int tid  = threadIdx.x;

    if (tid < G) s_n[tid] = g_list[grp * G + tid];
    if (tid == 0) s_img = g_gimg[grp];
    __syncthreads();

    if (s_n[0] < 0) return;   // unused group

    int n_r[G];
#pragma unroll
    for (int i = 0; i < G; i++) n_r[i] = s_n[i];

    // packed coords for this block's 8192 pixels -> registers
    unsigned cw0[32], cw1[32];
#pragma unroll
    for (int q = 0; q < 32; q++) {
        const int n = n_r[q >> 2];
        if (n >= 0) {
            const uint2 c = g_coords[(size_t)n * NPIX + ((q & 3) << 8) + tid];
            cw0[q] = c.x; cw1[q] = c.y;
        } else { cw0[q] = 0; cw1[q] = 0; }
    }

    const int c2beg = half * 16;
    const u64* src0 = g_imgH + ((size_t)(s_img * 32 + c2beg) << 12);
    const unsigned sb0 = (unsigned)__cvta_generic_to_shared(&tile[0][0]);

    // prologue: stage first tile (contiguous, conflict-free)
    {
        const char* src = (const char*)src0;
#pragma unroll
        for (int j = 0; j < 8; j++)
            CP16(sb0 + (tid + 256 * j) * 16, src + (tid + 256 * j) * 16);
        asm volatile("cp.async.commit_group;");
    }

    for (int ci = 0; ci < 16; ci++) {
        if (ci < 15) {
            const unsigned db = sb0 + ((ci + 1) & 1) * (IMPIX * 8);
            const char* src = (const char*)(src0 + ((size_t)(ci + 1) << 12));
#pragma unroll
            for (int j = 0; j < 8; j++)
                CP16(db + (tid + 256 * j) * 16, src + (tid + 256 * j) * 16);
            asm volatile("cp.async.commit_group;");
            asm volatile("cp.async.wait_group 1;");
        } else {
            asm volatile("cp.async.wait_group 0;");
        }
        __syncthreads();

        const uint2* tl = (const uint2*)&tile[ci & 1][0];
        const int c = (c2beg + ci) * 2;      // channels c, c+1, c+64, c+65
#pragma unroll
        for (int q = 0; q < 32; q++) {
            const int n = n_r[q >> 2];
            if (n < 0) continue;
            const unsigned a = cw0[q], b = cw1[q];
            const int o  = a & 0xFFF;
            const int dx = (a >> 12) & 1;
            const int dy = ((a >> 13) & 1) << 6;
            const float wx = (float)(b & 0xFFFF) * (1.f / 65535.f);
            const float wy = (float)(b >> 16)    * (1.f / 65535.f);

            const uint2 q00 = tl[o];
            const uint2 q01 = tl[o + dx];
            const uint2 q10 = tl[o + dy];
            const uint2 q11 = tl[o + dy + dx];

            const float2 a00 = __half22float2(*(const __half2*)&q00.x);
            const float2 a01 = __half22float2(*(const __half2*)&q01.x);
            const float2 a10 = __half22float2(*(const __half2*)&q10.x);
            const float2 a11 = __half22float2(*(const __half2*)&q11.x);
            const float2 b00 = __half22float2(*(const __half2*)&q00.y);
            const float2 b01 = __half22float2(*(const __half2*)&q01.y);
            const float2 b10 = __half22float2(*(const __half2*)&q10.y);
            const float2 b11 = __half22float2(*(const __half2*)&q11.y);

            // bilinear per channel slot
            float t0, t1, r0, r1, r2, r3;
            t0 = a00.x + wx * (a01.x - a00.x); t1 = a10.x + wx * (a11.x - a10.x);
            r0 = t0 + wy * (t1 - t0);                                  // ch c
            t0 = b00.x + wx * (b01.x - b00.x); t1 = b10.x + wx * (b11.x - b10.x);
            r1 = t0 + wy * (t1 - t0);                                  // ch c+1
            t0 = a00.y + wx * (a01.y - a00.y); t1 = a10.y + wx * (a11.y - a10.y);
            r2 = t0 + wy * (t1 - t0);                                  // ch c+64
            t0 = b00.y + wx * (b01.y - b00.y); t1 = b10.y + wx * (b11.y - b10.y);
            r3 = t0 + wy * (t1 - t0);                                  // ch c+65

            float* op = out + ((size_t)(unsigned)n << 17) + ((size_t)c << 10)
                            + ((q & 3) << 8) + tid;
            op[0]          = r0;
            op[1 << 10]    = r1;
            op[64 << 10]   = r2;
            op[65 << 10]   = r3;
        }
        __syncthreads();
    }
}

// ---------------- launch ----------------
extern "C" void kernel_launch(void* const* d_in, const int* in_sizes, int n_in,
                              void* d_out, int out_size)
{
    const float* polargrid = (const float*)d_in[0];
    const float* xt        = (const float*)d_in[1];
    const float* imgs      = (const float*)d_in[2];
    const int*   imgIDs    = (const int*)  d_in[3];
    const float* W1 = (const float*)d_in[4];
    const float* b1 = (const float*)d_in[5];
    const float* W2 = (const float*)d_in[6];
    const float* b2 = (const float*)d_in[7];
    const float* W3 = (const float*)d_in[8];
    const float* b3 = (const float*)d_in[9];
    const float* W4 = (const float*)d_in[10];
    const float* b4 = (const float*)d_in[11];
    float* out = (float*)d_out;

    float *h1, *h2, *h3, *theta, *part;
    cudaGetSymbolAddress((void**)&h1, g_h1);
    cudaGetSymbolAddress((void**)&h2, g_h2);
    cudaGetSymbolAddress((void**)&h3, g_h3);
    cudaGetSymbolAddress((void**)&theta, g_theta);
    cudaGetSymbolAddress((void**)&part, g_part);

    prep_groups<<<1, 256>>>(imgIDs);
    convert_kernel<<<256, 256>>>(imgs);

    // MLP: split-K partial + epilogue
    gemm_partial<<<dim3(512 / GBN, NB / GBM, KS), 256>>>(xt, W1, part, NB, 512, 3200, 3200 / KS);
    gemm_epi<0><<<NB * 512 / 256, 256>>>(part, b1, h1, NB * 512, 512);

    gemm_partial<<<dim3(256 / GBN, NB / GBM, KS), 256>>>(h1, W2, part, NB, 256, 512, 512 / KS);
    gemm_epi<0><<<NB * 256 / 256, 256>>>(part, b2, h2, NB * 256, 256);

    gemm_partial<<<dim3(256 / GBN, NB / GBM, KS), 256>>>(h2, W3, part, NB, 256, 256, 256 / KS);
    gemm_epi<0><<<NB * 256 / 256, 256>>>(part, b3, h3, NB * 256, 256);

    gemm_partial<<<dim3(1, NB / GBM, KS), 256>>>(h3, W4, part, NB, 36, 256, 256 / KS);
    gemm_epi<1><<<(NB * 36 + 255) / 256, 256>>>(part, b4, theta, NB * 36, 36);

    coords_kernel<<<NB, 256>>>(polargrid);
    sample_kernel<<<NGROUPS * 2, 256>>>(out);
}